// round 6
// baseline (speedup 1.0000x reference)
#include <cuda_runtime.h>

#define B_   8
#define S_   32
#define D_   256
#define M_   2048
#define GPB  16      // blocks per batch
#define RPB  128     // rows per block
#define NT   256     // threads per block
#define PST  272     // floats per partial record
#define NBLK (B_*GPB)
#define CNT_TOT (2*B_*S_ + 2)
#define NEGINF (__int_as_float(0xff800000))

// ----------------------------- device state -----------------------------
__device__ float g_mem [B_*M_*D_];        // only dirty rows ever written
__device__ float g_qt  [B_*S_*D_];        // (x@Wq+bq)@Wk^T / sqrt(D)
__device__ float g_xg  [B_*S_*D_];        // x@Wg1 + bg
__device__ float g_bgc [D_];              // bv@Wg2
__device__ float g_C   [D_*D_];           // Wv@Wg2
__device__ float g_part[2*B_*GPB*PST];    // partials, double buffered by step parity
__device__ int   g_tidx[2*B_*GPB*8];      // top8 global row ids
__device__ float g_gv  [B_*D_];           // gate vector per batch
__device__ int   g_cnt [CNT_TOT];         // cA[256], cB[256], cI, cD (self-resetting)

__device__ __forceinline__ int ldacq(const int* p) {
    int v;
    asm volatile("ld.acquire.gpu.global.b32 %0, [%1];" : "=r"(v) : "l"(p) : "memory");
    return v;
}
// release-arrive without the L1D-flushing CCTL.IVALL of __threadfence()
__device__ __forceinline__ void red_release(int* p) {
    asm volatile("red.release.gpu.global.add.s32 [%0], %1;" :: "l"(p), "r"(1) : "memory");
}

// ----------------------------- fused persistent kernel -----------------------------
__global__ void __launch_bounds__(NT, 1)
mal_fused(const float* __restrict__ x, const float* __restrict__ memory,
          const float* __restrict__ Wq, const float* __restrict__ bq,
          const float* __restrict__ Wk, const float* __restrict__ Wv,
          const float* __restrict__ bv, const float* __restrict__ Wg,
          const float* __restrict__ bg, float* __restrict__ out)
{
    __shared__ float s_wacc[8][D_];               // also init scratch (8KB)
    __shared__ float s_q[D_];
    __shared__ float s_lg[128];
    __shared__ float s_e[128];
    __shared__ float s_r8[8];
    __shared__ float s_cv[128];
    __shared__ int   s_ci[128];
    __shared__ unsigned long long s_pk[128];
    __shared__ int   s_rk[NT];
    __shared__ int   s_sel[8];
    __shared__ int   s_dirty[128];                // persistent copy-on-write flags
    __shared__ float s_p[D_];
    __shared__ float s_red[NT];
    __shared__ float s_scale[16];
    __shared__ float s_bm, s_invS;

    const int tid  = threadIdx.x, lane = tid & 31, warp = tid >> 5;
    const int bid  = blockIdx.x;
    const int b    = bid >> 4;
    const int blk  = bid & 15;
    int* cA        = g_cnt + b * S_;
    int* cB        = g_cnt + B_*S_ + b * S_;
    int* cI        = g_cnt + 2*B_*S_;
    int* cD        = g_cnt + 2*B_*S_ + 1;
    const int d0   = lane * 4;
    const int d1   = 128 + lane * 4;

    if (tid < 128) s_dirty[tid] = 0;

    // ================= init phase (distributed GEMVs) =================
    float* s_buf = &s_wacc[0][0];                 // 2048-float scratch
    if (bid < 96) {
        const int which = bid >> 5;               // 0: qt-chain, 1: xg, 2: C
        const int sub   = bid & 31;
        const int r0    = sub * 8;
        const float* srcA = (which == 2) ? (Wv + r0*D_) : (x + r0*D_);
        for (int i = tid; i < 2048; i += NT) s_buf[i] = srcA[i];
        __syncthreads();
        const float* Wcol = (which == 0) ? Wq : (which == 1 ? Wg : (Wg + D_*D_));
        float acc[8];
        #pragma unroll
        for (int r = 0; r < 8; ++r) acc[r] = 0.f;
        #pragma unroll 16
        for (int j = 0; j < D_; ++j) {
            float w = Wcol[j*D_ + tid];
            #pragma unroll
            for (int r = 0; r < 8; ++r) acc[r] += s_buf[r*D_ + j] * w;
        }
        if (which == 1) {
            float bb = bg[tid];
            #pragma unroll
            for (int r = 0; r < 8; ++r) g_xg[(r0+r)*D_ + tid] = acc[r] + bb;
        } else if (which == 2) {
            #pragma unroll
            for (int r = 0; r < 8; ++r) g_C[(r0+r)*D_ + tid] = acc[r];
        } else {
            // tmpq -> smem (overwrite x rows), then qt = tmpq @ Wk^T / sqrt(D)
            float bb = bq[tid];
            __syncthreads();
            #pragma unroll
            for (int r = 0; r < 8; ++r) s_buf[r*D_ + tid] = acc[r] + bb;
            __syncthreads();
            float4 t0[8], t1[8];
            #pragma unroll
            for (int r = 0; r < 8; ++r) {
                t0[r] = *(const float4*)(s_buf + r*D_ + lane*4);
                t1[r] = *(const float4*)(s_buf + r*D_ + 128 + lane*4);
            }
            int d = warp * 32;
            float4 w0 = *(const float4*)(Wk + d*D_ + lane*4);
            float4 w1 = *(const float4*)(Wk + d*D_ + 128 + lane*4);
            for (int dd = 0; dd < 32; ++dd) {
                float4 c0 = w0, c1 = w1;
                if (dd < 31) {
                    w0 = *(const float4*)(Wk + (d+1)*D_ + lane*4);
                    w1 = *(const float4*)(Wk + (d+1)*D_ + 128 + lane*4);
                }
                float dt[8];
                #pragma unroll
                for (int r = 0; r < 8; ++r) {
                    dt[r] = t0[r].x*c0.x + t0[r].y*c0.y + t0[r].z*c0.z + t0[r].w*c0.w
                          + t1[r].x*c1.x + t1[r].y*c1.y + t1[r].z*c1.z + t1[r].w*c1.w;
                    #pragma unroll
                    for (int o = 16; o; o >>= 1) dt[r] += __shfl_xor_sync(0xffffffffu, dt[r], o);
                }
                if (lane == 0) {
                    #pragma unroll
                    for (int r = 0; r < 8; ++r) g_qt[(r0+r)*D_ + d] = dt[r] * 0.0625f;
                }
                ++d;
            }
        }
    } else if (bid == 96) {
        float acc = 0.f;
        #pragma unroll 16
        for (int j = 0; j < D_; ++j) acc += bv[j] * Wg[(D_ + j)*D_ + tid];
        g_bgc[tid] = acc;
    }
    // global init barrier (fan-in 128)
    __syncthreads();
    if (tid == 0) {
        red_release(cI);
        while (ldacq(cI) < NBLK) { }
    }
    __syncthreads();

    // ================= main sequential loop =================
    const int rbase = blk * RPB + warp * 16;
    const float* bMem = memory + rbase * D_;
    const float* bG   = g_mem + (b*M_ + rbase) * D_;

    for (int t = 0; t < S_; ++t) {
        const int buf  = t & 1;
        float* part    = g_part + buf*(B_*GPB*PST) + bid * PST;
        int*   tidx    = g_tidx + buf*(B_*GPB*8);

        // ---- apply previous step's gated top-8 updates (copy-on-write) ----
        if (t > 0) {
            bool ownany = false;
            #pragma unroll
            for (int k = 0; k < 8; ++k) if ((s_sel[k] >> 7) == blk) ownany = true;
            if (ownany) {
                if (tid == 0) { while (ldacq(&cB[t-1]) < GPB) { } }
                __syncthreads();
                float gd   = __ldcg(&g_gv[b*D_ + tid]);
                float xd   = __ldg(&x[(b*S_ + (t-1))*D_ + tid]);
                float keep = 1.0f - gd, add = gd * xd;
                #pragma unroll
                for (int k = 0; k < 8; ++k) {
                    int gi = s_sel[k];
                    if ((gi >> 7) == blk) {
                        int li = gi & 127;
                        const float* src = s_dirty[li] ? (g_mem + (b*M_ + gi)*D_)
                                                       : (memory + gi*D_);
                        g_mem[(b*M_ + gi)*D_ + tid] = keep * src[tid] + add;
                    }
                }
                if (tid == 0) {
                    #pragma unroll
                    for (int k = 0; k < 8; ++k)
                        if ((s_sel[k] >> 7) == blk) s_dirty[s_sel[k] & 127] = 1;
                }
            }
        }
        s_q[tid] = g_qt[(b*S_ + t)*D_ + tid];
        __syncthreads();

        // ---- pass 1: own 128 rows -> regs, all 128 logits ----
        const float q0 = s_q[d0],   q1 = s_q[d0+1], q2 = s_q[d0+2], q3 = s_q[d0+3];
        const float q4 = s_q[d1],   q5 = s_q[d1+1], q6 = s_q[d1+2], q7 = s_q[d1+3];
        float4 ra[16], rb[16];
        #pragma unroll
        for (int r = 0; r < 16; ++r) {
            const float* rp = s_dirty[warp*16 + r] ? (bG + r*D_) : (bMem + r*D_);
            ra[r] = *(const float4*)(rp + d0);
            rb[r] = *(const float4*)(rp + d1);
            float dt = ra[r].x*q0 + ra[r].y*q1 + ra[r].z*q2 + ra[r].w*q3
                     + rb[r].x*q4 + rb[r].y*q5 + rb[r].z*q6 + rb[r].w*q7;
            #pragma unroll
            for (int o = 16; o; o >>= 1) dt += __shfl_xor_sync(0xffffffffu, dt, o);
            if (lane == 0) s_lg[warp*16 + r] = dt;
        }
        __syncthreads();

        // ---- block max, exp table, per-warp sums ----
        float v = (tid < 128) ? s_lg[tid] : NEGINF;
        {
            float m = v;
            #pragma unroll
            for (int o = 16; o; o >>= 1) m = fmaxf(m, __shfl_xor_sync(0xffffffffu, m, o));
            if (lane == 0) s_r8[warp] = m;
        }
        __syncthreads();
        if (tid == 0) {
            float bm = s_r8[0];
            #pragma unroll
            for (int w = 1; w < 8; ++w) bm = fmaxf(bm, s_r8[w]);
            s_bm = bm;
        }
        __syncthreads();
        const float bm = s_bm;
        float e = (tid < 128) ? __expf(v - bm) : 0.f;
        if (tid < 128) s_e[tid] = e;
        {
            float se = e;
            #pragma unroll
            for (int o = 16; o; o >>= 1) se += __shfl_xor_sync(0xffffffffu, se, o);
            if (lane == 0) s_r8[warp] = se;
        }
        if (tid < 128) {
            unsigned fb = __float_as_uint(v);
            fb ^= (fb & 0x80000000u) ? 0xFFFFFFFFu : 0x80000000u;
            s_pk[tid] = ((unsigned long long)fb << 32) | (unsigned)(~tid);
        }
        __syncthreads();

        // ---- pass 2: weighted row sum from registers + split local rank ----
        {
            float4 A = {0,0,0,0}, Bb = {0,0,0,0};
            #pragma unroll
            for (int r = 0; r < 16; ++r) {
                float er = s_e[warp*16 + r];
                A.x += er*ra[r].x; A.y += er*ra[r].y; A.z += er*ra[r].z; A.w += er*ra[r].w;
                Bb.x += er*rb[r].x; Bb.y += er*rb[r].y; Bb.z += er*rb[r].z; Bb.w += er*rb[r].w;
            }
            *(float4*)&s_wacc[warp][d0] = A;
            *(float4*)&s_wacc[warp][d1] = Bb;
        }
        {
            const int c  = tid & 127;
            const int j0 = (tid >> 7) * 64;
            unsigned long long me = s_pk[c];
            int rk = 0;
            #pragma unroll 16
            for (int j = 0; j < 64; ++j) rk += (s_pk[j0 + j] > me);
            s_rk[tid] = rk;
        }
        __syncthreads();
        {
            float pv = 0.f;
            #pragma unroll
            for (int w = 0; w < 8; ++w) pv += s_wacc[w][tid];
            part[2 + tid] = pv;
            if (tid == 0) {
                float sw = 0.f;
                #pragma unroll
                for (int w = 0; w < 8; ++w) sw += s_r8[w];
                part[0] = bm; part[1] = sw;
            }
        }
        if (tid < 128) {
            int rk = s_rk[tid] + s_rk[tid + 128];
            if (rk < 8) {
                part[258 + rk] = s_lg[tid];
                tidx[bid*8 + rk] = blk*RPB + tid;
            }
        }
        __syncthreads();
        if (tid == 0) {
            red_release(&cA[t]);
            while (ldacq(&cA[t]) < GPB) { }
        }
        __syncthreads();

        // ---- merge 16 partials (redundant per block) ----
        if (warp == 0) {
            float bmv = (lane < 16) ? __ldcg(&g_part[buf*(B_*GPB*PST) + (b*GPB + lane)*PST])     : NEGINF;
            float swv = (lane < 16) ? __ldcg(&g_part[buf*(B_*GPB*PST) + (b*GPB + lane)*PST + 1]) : 0.f;
            float Mx = bmv;
            #pragma unroll
            for (int o = 16; o; o >>= 1) Mx = fmaxf(Mx, __shfl_xor_sync(0xffffffffu, Mx, o));
            float sc = (lane < 16) ? __expf(bmv - Mx) : 0.f;
            if (lane < 16) s_scale[lane] = sc;
            float Ssum = sc * swv;
            #pragma unroll
            for (int o = 16; o; o >>= 1) Ssum += __shfl_xor_sync(0xffffffffu, Ssum, o);
            if (lane == 0) s_invS = 1.0f / Ssum;
        } else if (warp >= 4) {
            int ii = tid - 128;
            int i = ii >> 3, j = ii & 7;
            s_cv[ii] = __ldcg(&g_part[buf*(B_*GPB*PST) + (b*GPB + i)*PST + 258 + j]);
            s_ci[ii] = __ldcg(&g_tidx[buf*(B_*GPB*8) + (b*GPB + i)*8 + j]);
        }
        __syncthreads();
        {
            float pv = 0.f;
            #pragma unroll
            for (int i = 0; i < 16; ++i)
                pv += __ldcg(&g_part[buf*(B_*GPB*PST) + (b*GPB + i)*PST + 2 + tid]) * s_scale[i];
            s_p[tid] = pv * s_invS;
        }
        if (tid < 128) {
            unsigned fb = __float_as_uint(s_cv[tid]);
            fb ^= (fb & 0x80000000u) ? 0xFFFFFFFFu : 0x80000000u;
            s_pk[tid] = ((unsigned long long)fb << 32) | (unsigned)(~s_ci[tid]);
        }
        __syncthreads();

        // ---- global top-8 rank overlapped with slice GEMV ----
        {
            const int c  = tid & 127;
            const int j0 = (tid >> 7) * 64;
            unsigned long long me = s_pk[c];
            int rk = 0;
            #pragma unroll 16
            for (int j = 0; j < 64; ++j) rk += (s_pk[j0 + j] > me);
            s_rk[tid] = rk;
        }
        {
            const int dbase = blk * 16;
            const float* Mp = (lane < 16) ? (Wv + dbase + lane)
                                          : (g_C + dbase + (lane - 16));
            float acc = 0.f;
            const int k0 = warp * 32;
            #pragma unroll
            for (int kk = 0; kk < 32; ++kk)
                acc += s_p[k0 + kk] * Mp[(k0 + kk)*D_];
            s_red[tid] = acc;
        }
        __syncthreads();
        if (tid < 128) {
            int rk = s_rk[tid] + s_rk[tid + 128];
            if (rk < 8) s_sel[rk] = s_ci[tid];
        }
        if (tid < 32) {
            float tot = 0.f;
            #pragma unroll
            for (int w = 0; w < 8; ++w) tot += s_red[w*32 + tid];
            const int dbase = blk * 16;
            if (tid < 16) {
                out[(b*S_ + t)*D_ + dbase + tid] = tot + __ldg(&bv[dbase + tid]);
            } else {
                int d = dbase + tid - 16;
                float z = g_xg[(b*S_ + t)*D_ + d] + g_bgc[d] + tot;
                g_gv[b*D_ + d] = 1.0f / (1.0f + __expf(-z));
            }
        }
        __syncthreads();
        if (tid == 0) red_release(&cB[t]);   // owners wait at t+1
    }

    // ================= self-reset counters for next launch =================
    __syncthreads();
    if (tid == 0) red_release(cD);
    if (bid == 0) {
        if (tid == 0) { while (ldacq(cD) < NBLK) { } }
        __syncthreads();
        for (int i = tid; i < CNT_TOT; i += NT) g_cnt[i] = 0;
    }
}

// ----------------------------- launch -----------------------------
extern "C" void kernel_launch(void* const* d_in, const int* in_sizes, int n_in,
                              void* d_out, int out_size)
{
    const float* x      = (const float*)d_in[0];
    const float* memory = (const float*)d_in[1];
    const float* Wq     = (const float*)d_in[2];
    const float* bq     = (const float*)d_in[3];
    const float* Wk     = (const float*)d_in[4];
    // d_in[5] = bk : constant logit shift; softmax/top-k invariant -> unused
    const float* Wv     = (const float*)d_in[6];
    const float* bv     = (const float*)d_in[7];
    const float* Wg     = (const float*)d_in[8];
    const float* bg     = (const float*)d_in[9];
    float* out = (float*)d_out;

    mal_fused<<<NBLK, NT>>>(x, memory, Wq, bq, Wk, Wv, bv, Wg, bg, out);
}